// round 13
// baseline (speedup 1.0000x reference)
#include <cuda_runtime.h>
#include <cuda_bf16.h>

// out[b,c,t,l] = (x[b,c,i0,l] + x[b,c,i1,l] + x[b,c,i2,l]) / 3
// x: (32, 2, 24, 32768) fp32, out: (32, 2, 30, 32768) fp32
//
// R5 body (banded 2-row sliding window, 32 regs, 8 CTAs/SM, default loads,
// __stcs stores) + ALL-ROWS prefetch.global.L2 up front. Prefetches deepen
// the DRAM read queue WITHOUT consuming registers or scoreboard slots,
// breaking the register<->lookahead-depth coupling that capped R10-R12.
// Demand loads then hit L2. Same traffic, earlier reads, high occupancy
// AND deep lookahead simultaneously.

#define NV 24
#define NT 30
#define L  32768
#define L4 (L / 4)
#define TPB 256

__global__ __launch_bounds__(TPB, 8)
void tri_mean_kernel(const float4* __restrict__ x, float4* __restrict__ out) {
    const int col = blockIdx.x * TPB + threadIdx.x;   // 0 .. L4-1
    const int bc  = blockIdx.y;                       // 0 .. 63

    const float4* __restrict__ xb = x   + (size_t)bc * NV * L4 + col;
    float4* __restrict__ ob       = out + (size_t)bc * NT * L4 + col;

    const float s = 1.0f / 3.0f;

    // Prefetch every vertex row into L2 immediately: 24 line-fetches in
    // flight per warp with zero register cost. One lane per 128B line is
    // enough (8 threads share a line).
    if ((threadIdx.x & 7) == 0) {
#pragma unroll
        for (int i = 0; i < NV; i++) {
            asm volatile("prefetch.global.L2 [%0];" :: "l"(xb + (size_t)i * L4));
        }
    }

#define LD(i)  xb[(size_t)(i) * L4]
#define EMIT(t, a, b, c) do {                        \
        float4 _r;                                   \
        _r.x = ((a).x + (b).x + (c).x) * s;          \
        _r.y = ((a).y + (b).y + (c).y) * s;          \
        _r.z = ((a).z + (b).z + (c).z) * s;          \
        _r.w = ((a).w + (b).w + (c).w) * s;          \
        __stcs(&ob[(size_t)(t) * L4], _r);           \
    } while (0)

    float4 A0, A1, A2, A3, B0, B1, B2, B3;

    // row0 (3): v0,v1,v2   row1 (4): v3,v4,v5,v6
    A0 = LD(0);  A1 = LD(1);  A2 = LD(2);
    B0 = LD(3);  B1 = LD(4);  B2 = LD(5);  B3 = LD(6);
    // band0: (0,3,4),(0,1,4),(1,4,5),(1,2,5),(2,5,6)
    EMIT(0, A0, B0, B1);
    EMIT(1, A0, A1, B1);
    EMIT(2, A1, B1, B2);
    EMIT(3, A1, A2, B2);
    EMIT(4, A2, B2, B3);

    // A = row1 (4), load row2 (3): v7,v8,v9
    A0 = B0; A1 = B1; A2 = B2; A3 = B3;
    B0 = LD(7);  B1 = LD(8);  B2 = LD(9);
    // band1: (3,4,7),(4,7,8),(4,5,8),(5,8,9),(5,6,9)
    EMIT(5, A0, A1, B0);
    EMIT(6, A1, B0, B1);
    EMIT(7, A1, A2, B1);
    EMIT(8, A2, B1, B2);
    EMIT(9, A2, A3, B2);

    // A = row2 (3), load row3 (4): v10..v13
    A0 = B0; A1 = B1; A2 = B2;
    B0 = LD(10); B1 = LD(11); B2 = LD(12); B3 = LD(13);
    // band2: (7,10,11),(7,8,11),(8,11,12),(8,9,12),(9,12,13)
    EMIT(10, A0, B0, B1);
    EMIT(11, A0, A1, B1);
    EMIT(12, A1, B1, B2);
    EMIT(13, A1, A2, B2);
    EMIT(14, A2, B2, B3);

    // A = row3 (4), load row4 (3): v14..v16
    A0 = B0; A1 = B1; A2 = B2; A3 = B3;
    B0 = LD(14); B1 = LD(15); B2 = LD(16);
    // band3: (10,11,14),(11,14,15),(11,12,15),(12,15,16),(12,13,16)
    EMIT(15, A0, A1, B0);
    EMIT(16, A1, B0, B1);
    EMIT(17, A1, A2, B1);
    EMIT(18, A2, B1, B2);
    EMIT(19, A2, A3, B2);

    // A = row4 (3), load row5 (4): v17..v20
    A0 = B0; A1 = B1; A2 = B2;
    B0 = LD(17); B1 = LD(18); B2 = LD(19); B3 = LD(20);
    // band4: (14,17,18),(14,15,18),(15,18,19),(15,16,19),(16,19,20)
    EMIT(20, A0, B0, B1);
    EMIT(21, A0, A1, B1);
    EMIT(22, A1, B1, B2);
    EMIT(23, A1, A2, B2);
    EMIT(24, A2, B2, B3);

    // A = row5 (4), load row6 (3): v21..v23
    A0 = B0; A1 = B1; A2 = B2; A3 = B3;
    B0 = LD(21); B1 = LD(22); B2 = LD(23);
    // band5: (17,18,21),(18,21,22),(18,19,22),(19,22,23),(19,20,23)
    EMIT(25, A0, A1, B0);
    EMIT(26, A1, B0, B1);
    EMIT(27, A1, A2, B1);
    EMIT(28, A2, B1, B2);
    EMIT(29, A2, A3, B2);

#undef LD
#undef EMIT
}

extern "C" void kernel_launch(void* const* d_in, const int* in_sizes, int n_in,
                              void* d_out, int out_size) {
    const float4* x = (const float4*)d_in[0];
    float4* out = (float4*)d_out;

    dim3 block(TPB);
    dim3 grid(L4 / TPB, 64);  // (32, 64) = 2048 blocks
    tri_mean_kernel<<<grid, block>>>(x, out);
}

// round 14
// speedup vs baseline: 1.1545x; 1.1545x over previous
#include <cuda_runtime.h>
#include <cuda_bf16.h>

// out[b,c,t,l] = (x[b,c,i0,l] + x[b,c,i1,l] + x[b,c,i2,l]) / 3
// x: (32, 2, 24, 32768) fp32, out: (32, 2, 30, 32768) fp32
//
// R5 body (banded 2-row window, 32 regs, 8 CTAs/SM, default loads, __stcs
// stores) + ONE-ROW-AHEAD prefetch.global.L2: at band k, demand-load row k+1
// and prefetch row k+2. Bounded distance: ~4.7MB outstanding chip-wide
// (<< 126MB L2) -> no thrash (R13's all-rows storm refetched ~140MB).
// Decouples read lookahead from the register file: 64 warps/SM AND ~2-row
// depth simultaneously.

#define NV 24
#define NT 30
#define L  32768
#define L4 (L / 4)
#define TPB 256

__global__ __launch_bounds__(TPB, 8)
void tri_mean_kernel(const float4* __restrict__ x, float4* __restrict__ out) {
    const int col = blockIdx.x * TPB + threadIdx.x;   // 0 .. L4-1
    const int bc  = blockIdx.y;                       // 0 .. 63

    const float4* __restrict__ xb = x   + (size_t)bc * NV * L4 + col;
    float4* __restrict__ ob       = out + (size_t)bc * NT * L4 + col;

    const float s = 1.0f / 3.0f;
    const bool pf = (threadIdx.x & 7) == 0;   // one lane per 128B line

#define LD(i)  xb[(size_t)(i) * L4]
#define PF(i)  do { if (pf) asm volatile("prefetch.global.L2 [%0];" \
                        :: "l"(xb + (size_t)(i) * L4)); } while (0)
#define EMIT(t, a, b, c) do {                        \
        float4 _r;                                   \
        _r.x = ((a).x + (b).x + (c).x) * s;          \
        _r.y = ((a).y + (b).y + (c).y) * s;          \
        _r.z = ((a).z + (b).z + (c).z) * s;          \
        _r.w = ((a).w + (b).w + (c).w) * s;          \
        __stcs(&ob[(size_t)(t) * L4], _r);           \
    } while (0)

    float4 A0, A1, A2, A3, B0, B1, B2, B3;

    // Rows: r0(0,3) r1(3,4) r2(7,3) r3(10,4) r4(14,3) r5(17,4) r6(21,3)
    A0 = LD(0);  A1 = LD(1);  A2 = LD(2);              // r0 demand
    B0 = LD(3);  B1 = LD(4);  B2 = LD(5);  B3 = LD(6); // r1 demand
    PF(7); PF(8); PF(9);                               // r2 prefetch
    // band0: (0,3,4),(0,1,4),(1,4,5),(1,2,5),(2,5,6)
    EMIT(0, A0, B0, B1);
    EMIT(1, A0, A1, B1);
    EMIT(2, A1, B1, B2);
    EMIT(3, A1, A2, B2);
    EMIT(4, A2, B2, B3);

    // A<-r1; demand r2 (prefetched); prefetch r3
    A0 = B0; A1 = B1; A2 = B2; A3 = B3;
    B0 = LD(7);  B1 = LD(8);  B2 = LD(9);
    PF(10); PF(11); PF(12); PF(13);
    // band1: (3,4,7),(4,7,8),(4,5,8),(5,8,9),(5,6,9)
    EMIT(5, A0, A1, B0);
    EMIT(6, A1, B0, B1);
    EMIT(7, A1, A2, B1);
    EMIT(8, A2, B1, B2);
    EMIT(9, A2, A3, B2);

    // A<-r2; demand r3; prefetch r4
    A0 = B0; A1 = B1; A2 = B2;
    B0 = LD(10); B1 = LD(11); B2 = LD(12); B3 = LD(13);
    PF(14); PF(15); PF(16);
    // band2: (7,10,11),(7,8,11),(8,11,12),(8,9,12),(9,12,13)
    EMIT(10, A0, B0, B1);
    EMIT(11, A0, A1, B1);
    EMIT(12, A1, B1, B2);
    EMIT(13, A1, A2, B2);
    EMIT(14, A2, B2, B3);

    // A<-r3; demand r4; prefetch r5
    A0 = B0; A1 = B1; A2 = B2; A3 = B3;
    B0 = LD(14); B1 = LD(15); B2 = LD(16);
    PF(17); PF(18); PF(19); PF(20);
    // band3: (10,11,14),(11,14,15),(11,12,15),(12,15,16),(12,13,16)
    EMIT(15, A0, A1, B0);
    EMIT(16, A1, B0, B1);
    EMIT(17, A1, A2, B1);
    EMIT(18, A2, B1, B2);
    EMIT(19, A2, A3, B2);

    // A<-r4; demand r5; prefetch r6
    A0 = B0; A1 = B1; A2 = B2;
    B0 = LD(17); B1 = LD(18); B2 = LD(19); B3 = LD(20);
    PF(21); PF(22); PF(23);
    // band4: (14,17,18),(14,15,18),(15,18,19),(15,16,19),(16,19,20)
    EMIT(20, A0, B0, B1);
    EMIT(21, A0, A1, B1);
    EMIT(22, A1, B1, B2);
    EMIT(23, A1, A2, B2);
    EMIT(24, A2, B2, B3);

    // A<-r5; demand r6
    A0 = B0; A1 = B1; A2 = B2; A3 = B3;
    B0 = LD(21); B1 = LD(22); B2 = LD(23);
    // band5: (17,18,21),(18,21,22),(18,19,22),(19,22,23),(19,20,23)
    EMIT(25, A0, A1, B0);
    EMIT(26, A1, B0, B1);
    EMIT(27, A1, A2, B1);
    EMIT(28, A2, B1, B2);
    EMIT(29, A2, A3, B2);

#undef LD
#undef PF
#undef EMIT
}

extern "C" void kernel_launch(void* const* d_in, const int* in_sizes, int n_in,
                              void* d_out, int out_size) {
    const float4* x = (const float4*)d_in[0];
    float4* out = (float4*)d_out;

    dim3 block(TPB);
    dim3 grid(L4 / TPB, 64);  // (32, 64) = 2048 blocks
    tri_mean_kernel<<<grid, block>>>(x, out);
}

// round 15
// speedup vs baseline: 1.3635x; 1.1811x over previous
#include <cuda_runtime.h>
#include <cuda_bf16.h>

// out[b,c,t,l] = (x[b,c,i0,l] + x[b,c,i1,l] + x[b,c,i2,l]) / 3
// x: (32, 2, 24, 32768) fp32, out: (32, 2, 30, 32768) fp32
//
// CONVERGED KERNEL (R11 of 14-round optimization):
//  - Banded sliding window over the 7 vertex rows / 6 triangle bands with
//    TWO-band register lookahead (4-row window): during each band's five
//    __stcs stores, the next two rows' loads are in flight.
//  - TPB=256, grid (32,64); launch_bounds(256,3) -> 80 regs, no spills.
//  - Loads: default policy (preserves ~50MB/replay incidental L2 warm hits;
//    .cs/.lu and prefetch.global.L2 all destroy it - measured).
//  - Stores: __stcs (output never re-read; keeps it from displacing input).
// Measured: 71.8us harness / 64.9us ncu, 6.07TB/s (76% of 8TB/s spec) =
// the mixed read/write turnaround floor for this access pattern.

#define NV 24
#define NT 30
#define L  32768
#define L4 (L / 4)
#define TPB 256

__global__ __launch_bounds__(TPB, 3)
void tri_mean_kernel(const float4* __restrict__ x, float4* __restrict__ out) {
    const int col = blockIdx.x * TPB + threadIdx.x;   // 0 .. L4-1
    const int bc  = blockIdx.y;                       // 0 .. 63

    const float4* __restrict__ xb = x   + (size_t)bc * NV * L4 + col;
    float4* __restrict__ ob       = out + (size_t)bc * NT * L4 + col;

    const float s = 1.0f / 3.0f;

#define LD(i)  xb[(size_t)(i) * L4]
#define EMIT(t, a, b, c) do {                        \
        float4 _r;                                   \
        _r.x = ((a).x + (b).x + (c).x) * s;          \
        _r.y = ((a).y + (b).y + (c).y) * s;          \
        _r.z = ((a).z + (b).z + (c).z) * s;          \
        _r.w = ((a).w + (b).w + (c).w) * s;          \
        __stcs(&ob[(size_t)(t) * L4], _r);           \
    } while (0)

    // 4-row window: A = row k, B = row k+1 (band k operands),
    //               C = row k+2, D = row k+3 (prefetched in registers).
    float4 A0, A1, A2, A3;
    float4 B0, B1, B2, B3;
    float4 C0, C1, C2, C3;
    float4 D0, D1, D2, D3;

    // Rows (start,size): r0(0,3) r1(3,4) r2(7,3) r3(10,4) r4(14,3) r5(17,4) r6(21,3)
    A0 = LD(0);  A1 = LD(1);  A2 = LD(2);               // r0
    B0 = LD(3);  B1 = LD(4);  B2 = LD(5);  B3 = LD(6);  // r1
    C0 = LD(7);  C1 = LD(8);  C2 = LD(9);               // r2
    D0 = LD(10); D1 = LD(11); D2 = LD(12); D3 = LD(13); // r3

    // band0 (r0:3 -> r1:4): (0,3,4),(0,1,4),(1,4,5),(1,2,5),(2,5,6)
    EMIT(0, A0, B0, B1);
    EMIT(1, A0, A1, B1);
    EMIT(2, A1, B1, B2);
    EMIT(3, A1, A2, B2);
    EMIT(4, A2, B2, B3);

    // slide: A<-r1(4), B<-r2(3), C<-r3(4); prefetch D<-r4(3)
    A0 = B0; A1 = B1; A2 = B2; A3 = B3;
    B0 = C0; B1 = C1; B2 = C2;
    C0 = D0; C1 = D1; C2 = D2; C3 = D3;
    D0 = LD(14); D1 = LD(15); D2 = LD(16);
    // band1 (r1:4 -> r2:3): (3,4,7),(4,7,8),(4,5,8),(5,8,9),(5,6,9)
    EMIT(5, A0, A1, B0);
    EMIT(6, A1, B0, B1);
    EMIT(7, A1, A2, B1);
    EMIT(8, A2, B1, B2);
    EMIT(9, A2, A3, B2);

    // slide: A<-r2(3), B<-r3(4), C<-r4(3); prefetch D<-r5(4)
    A0 = B0; A1 = B1; A2 = B2;
    B0 = C0; B1 = C1; B2 = C2; B3 = C3;
    C0 = D0; C1 = D1; C2 = D2;
    D0 = LD(17); D1 = LD(18); D2 = LD(19); D3 = LD(20);
    // band2 (r2:3 -> r3:4): (7,10,11),(7,8,11),(8,11,12),(8,9,12),(9,12,13)
    EMIT(10, A0, B0, B1);
    EMIT(11, A0, A1, B1);
    EMIT(12, A1, B1, B2);
    EMIT(13, A1, A2, B2);
    EMIT(14, A2, B2, B3);

    // slide: A<-r3(4), B<-r4(3), C<-r5(4); prefetch D<-r6(3)
    A0 = B0; A1 = B1; A2 = B2; A3 = B3;
    B0 = C0; B1 = C1; B2 = C2;
    C0 = D0; C1 = D1; C2 = D2; C3 = D3;
    D0 = LD(21); D1 = LD(22); D2 = LD(23);
    // band3 (r3:4 -> r4:3): (10,11,14),(11,14,15),(11,12,15),(12,15,16),(12,13,16)
    EMIT(15, A0, A1, B0);
    EMIT(16, A1, B0, B1);
    EMIT(17, A1, A2, B1);
    EMIT(18, A2, B1, B2);
    EMIT(19, A2, A3, B2);

    // slide: A<-r4(3), B<-r5(4), C<-r6(3)
    A0 = B0; A1 = B1; A2 = B2;
    B0 = C0; B1 = C1; B2 = C2; B3 = C3;
    C0 = D0; C1 = D1; C2 = D2;
    // band4 (r4:3 -> r5:4): (14,17,18),(14,15,18),(15,18,19),(15,16,19),(16,19,20)
    EMIT(20, A0, B0, B1);
    EMIT(21, A0, A1, B1);
    EMIT(22, A1, B1, B2);
    EMIT(23, A1, A2, B2);
    EMIT(24, A2, B2, B3);

    // slide: A<-r5(4), B<-r6(3)
    A0 = B0; A1 = B1; A2 = B2; A3 = B3;
    B0 = C0; B1 = C1; B2 = C2;
    // band5 (r5:4 -> r6:3): (17,18,21),(18,21,22),(18,19,22),(19,22,23),(19,20,23)
    EMIT(25, A0, A1, B0);
    EMIT(26, A1, B0, B1);
    EMIT(27, A1, A2, B1);
    EMIT(28, A2, B1, B2);
    EMIT(29, A2, A3, B2);

#undef LD
#undef EMIT
}

extern "C" void kernel_launch(void* const* d_in, const int* in_sizes, int n_in,
                              void* d_out, int out_size) {
    const float4* x = (const float4*)d_in[0];
    float4* out = (float4*)d_out;

    dim3 block(TPB);
    dim3 grid(L4 / TPB, 64);  // (32, 64) = 2048 blocks
    tri_mean_kernel<<<grid, block>>>(x, out);
}